// round 15
// baseline (speedup 1.0000x reference)
#include <cuda_runtime.h>
#include <math.h>

// Problem shape (fixed per reference)
#define NN   100000
#define NE   3200000
#define DIN  128
#define DH   16
#define DOUT 2
#define SCAN_BLK 1024
#define NPART ((NN + SCAN_BLK - 1) / SCAN_BLK)   // 98

// Scratch (static __device__ arrays: allocation-free rule)
static __device__ __align__(16) float g_h1[NN * DH];   // (x@W1)*dinv   6.4 MB
static __device__ __align__(8)  float g_h2[NN * DOUT]; // layer-2 msgs  0.8 MB
static __device__ int   g_srcs[NE];                    // CSR src list 12.8 MB
static __device__ int   g_deg[NN];
static __device__ int   g_incl[NN];                    // block-local inclusive scan
static __device__ int   g_rowstart[NN];
static __device__ int   g_cursor[NN];
static __device__ int   g_part[NPART];
static __device__ float g_dinv[NN];
static __device__ int   g_is64;   // 1 if edge_index is int64, 0 if int32

// ---------------------------------------------------------------------------
// Detect edge_index dtype (int64 vs int32), PARALLEL: 32 lanes each check one
// odd 32-bit word; int64 values < 2^17 have all-zero high words there.
// ---------------------------------------------------------------------------
__global__ void k_detect(const int* __restrict__ ei32) {
    int lane = threadIdx.x;
    int v = ei32[1 + 2 * lane];
    unsigned nz = __ballot_sync(0xFFFFFFFF, v != 0);
    if (lane == 0) g_is64 = (nz == 0) ? 1 : 0;
}

__device__ __forceinline__ void load_edge(const void* ei, int e, int& s, int& d) {
    if (g_is64) {
        s = (int)((const long long*)ei)[e];
        d = (int)((const long long*)ei)[(long long)NE + e];
    } else {
        s = ((const int*)ei)[e];
        d = ((const int*)ei)[NE + e];
    }
}

// ---------------------------------------------------------------------------
__global__ void k_zero() {
    int i = blockIdx.x * blockDim.x + threadIdx.x;
    if (i < NN) g_deg[i] = 0;
}

// Degree count over dst (only edges with both endpoints valid are kept).
__global__ void k_prep(const void* __restrict__ ei) {
    int e = blockIdx.x * blockDim.x + threadIdx.x;
    if (e >= NE) return;
    int s, d;
    load_edge(ei, e, s, d);
    if ((unsigned)s < NN && (unsigned)d < NN) atomicAdd(&g_deg[d], 1);
}

// ---------------------------------------------------------------------------
// Exclusive scan of deg -> rowstart (3 kernels), plus dinv and cursor.
// ---------------------------------------------------------------------------
__global__ void k_scan_a() {
    __shared__ int sh[SCAN_BLK];
    int i = blockIdx.x * SCAN_BLK + threadIdx.x;
    int v = (i < NN) ? g_deg[i] : 0;
    sh[threadIdx.x] = v;
    __syncthreads();
#pragma unroll
    for (int o = 1; o < SCAN_BLK; o <<= 1) {
        int t = (threadIdx.x >= o) ? sh[threadIdx.x - o] : 0;
        __syncthreads();
        sh[threadIdx.x] += t;
        __syncthreads();
    }
    if (i < NN) g_incl[i] = sh[threadIdx.x];
    if (threadIdx.x == SCAN_BLK - 1) g_part[blockIdx.x] = sh[SCAN_BLK - 1];
}

// Parallel exclusive scan of the 98 partials (128-thread Hillis-Steele).
__global__ void k_scan_b() {
    __shared__ int sh[128];
    int t = threadIdx.x;
    int v = (t < NPART) ? g_part[t] : 0;
    sh[t] = v;
    __syncthreads();
#pragma unroll
    for (int o = 1; o < 128; o <<= 1) {
        int u = (t >= o) ? sh[t - o] : 0;
        __syncthreads();
        sh[t] += u;
        __syncthreads();
    }
    if (t < NPART) g_part[t] = sh[t] - v;  // exclusive
}

__global__ void k_scan_c() {
    int i = blockIdx.x * blockDim.x + threadIdx.x;
    if (i >= NN) return;
    int deg = g_deg[i];
    int start = g_incl[i] - deg + g_part[i / SCAN_BLK];
    g_rowstart[i] = start;
    g_cursor[i]   = start;
    g_dinv[i]     = rsqrtf((float)deg + 1.0f);  // +1 = self-loop
}

// ---------------------------------------------------------------------------
// Reorder: group src indices by dst (CSR). Order within a row is arbitrary.
// ---------------------------------------------------------------------------
__global__ void k_reorder(const void* __restrict__ ei) {
    int e = blockIdx.x * blockDim.x + threadIdx.x;
    if (e >= NE) return;
    int s, d;
    load_edge(ei, e, s, d);
    if ((unsigned)s >= NN || (unsigned)d >= NN) return;
    int pos = atomicAdd(&g_cursor[d], 1);
    g_srcs[pos] = s;
}

// ---------------------------------------------------------------------------
// GEMM1: h1' = (x @ W1) * dinv[row]. Separable norm: msg = dinv[d]*h1'[s].
// ---------------------------------------------------------------------------
__global__ void k_gemm1(const float* __restrict__ x, const float* __restrict__ W1) {
    __shared__ float4 Ws[DIN * DH / 4];  // 8 KB, [k][c/4]
    const float4* w4 = (const float4*)W1;
    for (int i = threadIdx.x; i < DIN * DH / 4; i += blockDim.x) Ws[i] = w4[i];
    __syncthreads();

    int row = blockIdx.x * blockDim.x + threadIdx.x;
    if (row >= NN) return;

    const float4* xr = (const float4*)(x + (size_t)row * DIN);
    float4 a0 = make_float4(0.f, 0.f, 0.f, 0.f);
    float4 a1 = a0, a2 = a0, a3 = a0;

#pragma unroll 8
    for (int k4 = 0; k4 < DIN / 4; k4++) {
        float4 xq = __ldg(xr + k4);
        float xv[4] = {xq.x, xq.y, xq.z, xq.w};
#pragma unroll
        for (int kk = 0; kk < 4; kk++) {
            int k = k4 * 4 + kk;
            float v = xv[kk];
            float4 w0 = Ws[k * 4 + 0], w1 = Ws[k * 4 + 1];
            float4 w2 = Ws[k * 4 + 2], w3 = Ws[k * 4 + 3];
            a0.x += v * w0.x; a0.y += v * w0.y; a0.z += v * w0.z; a0.w += v * w0.w;
            a1.x += v * w1.x; a1.y += v * w1.y; a1.z += v * w1.z; a1.w += v * w1.w;
            a2.x += v * w2.x; a2.y += v * w2.y; a2.z += v * w2.z; a2.w += v * w2.w;
            a3.x += v * w3.x; a3.y += v * w3.y; a3.z += v * w3.z; a3.w += v * w3.w;
        }
    }
    float di = g_dinv[row];
    a0.x *= di; a0.y *= di; a0.z *= di; a0.w *= di;
    a1.x *= di; a1.y *= di; a1.z *= di; a1.w *= di;
    a2.x *= di; a2.y *= di; a2.z *= di; a2.w *= di;
    a3.x *= di; a3.y *= di; a3.z *= di; a3.w *= di;
    float4* o = (float4*)(g_h1 + (size_t)row * DH);
    o[0] = a0; o[1] = a1; o[2] = a2; o[3] = a3;
}

// ---------------------------------------------------------------------------
// Layer 1 fused (quad-per-dst): gather-sum h1'[src] in registers (unroll x4
// for MLP), add self, scale by dinv, +b1, relu, @W2, scale by dinv -> h2'.
// ---------------------------------------------------------------------------
__global__ void k_layer1(const float* __restrict__ b1, const float* __restrict__ W2) {
    __shared__ float W2s[DH * DOUT];
    __shared__ float b1s[DH];
    if (threadIdx.x < DH * DOUT) W2s[threadIdx.x] = W2[threadIdx.x];
    if (threadIdx.x < DH)        b1s[threadIdx.x] = b1[threadIdx.x];
    __syncthreads();

    int gid = blockIdx.x * blockDim.x + threadIdx.x;
    int i = gid >> 2;
    int q = gid & 3;
    if (i >= NN) return;

    int start = g_rowstart[i];
    int end   = start + g_deg[i];

    // self-loop contribution (h1'[i]) seeds accumulator 0
    float4 a0 = __ldg((const float4*)(g_h1 + (size_t)i * DH) + q);
    float4 a1 = make_float4(0.f, 0.f, 0.f, 0.f);
    float4 a2 = a1, a3 = a1;

    int j = start;
    for (; j + 3 < end; j += 4) {
        int s0 = __ldg(&g_srcs[j]);
        int s1 = __ldg(&g_srcs[j + 1]);
        int s2 = __ldg(&g_srcs[j + 2]);
        int s3 = __ldg(&g_srcs[j + 3]);
        float4 v0 = __ldg((const float4*)(g_h1 + (size_t)s0 * DH) + q);
        float4 v1 = __ldg((const float4*)(g_h1 + (size_t)s1 * DH) + q);
        float4 v2 = __ldg((const float4*)(g_h1 + (size_t)s2 * DH) + q);
        float4 v3 = __ldg((const float4*)(g_h1 + (size_t)s3 * DH) + q);
        a0.x += v0.x; a0.y += v0.y; a0.z += v0.z; a0.w += v0.w;
        a1.x += v1.x; a1.y += v1.y; a1.z += v1.z; a1.w += v1.w;
        a2.x += v2.x; a2.y += v2.y; a2.z += v2.z; a2.w += v2.w;
        a3.x += v3.x; a3.y += v3.y; a3.z += v3.z; a3.w += v3.w;
    }
    for (; j < end; j++) {
        int s0 = __ldg(&g_srcs[j]);
        float4 v0 = __ldg((const float4*)(g_h1 + (size_t)s0 * DH) + q);
        a0.x += v0.x; a0.y += v0.y; a0.z += v0.z; a0.w += v0.w;
    }
    a0.x += a1.x + a2.x + a3.x;
    a0.y += a1.y + a2.y + a3.y;
    a0.z += a1.z + a2.z + a3.z;
    a0.w += a1.w + a2.w + a3.w;

    float di = g_dinv[i];
    float r0 = fmaxf(di * a0.x + b1s[4 * q + 0], 0.f);
    float r1 = fmaxf(di * a0.y + b1s[4 * q + 1], 0.f);
    float r2 = fmaxf(di * a0.z + b1s[4 * q + 2], 0.f);
    float r3 = fmaxf(di * a0.w + b1s[4 * q + 3], 0.f);

    float h2a = r0 * W2s[(4 * q + 0) * 2 + 0] + r1 * W2s[(4 * q + 1) * 2 + 0]
              + r2 * W2s[(4 * q + 2) * 2 + 0] + r3 * W2s[(4 * q + 3) * 2 + 0];
    float h2b = r0 * W2s[(4 * q + 0) * 2 + 1] + r1 * W2s[(4 * q + 1) * 2 + 1]
              + r2 * W2s[(4 * q + 2) * 2 + 1] + r3 * W2s[(4 * q + 3) * 2 + 1];

    // quad reduction (width-4 shuffles)
    h2a += __shfl_down_sync(0xFFFFFFFF, h2a, 2, 4);
    h2a += __shfl_down_sync(0xFFFFFFFF, h2a, 1, 4);
    h2b += __shfl_down_sync(0xFFFFFFFF, h2b, 2, 4);
    h2b += __shfl_down_sync(0xFFFFFFFF, h2b, 1, 4);

    if (q == 0)
        *(float2*)(g_h2 + (size_t)i * DOUT) = make_float2(h2a * di, h2b * di);
}

// ---------------------------------------------------------------------------
// Layer 2 fused (thread-per-dst): gather-sum h2'[src] (unroll x4), add self,
// scale, +b2, log_softmax, write out.
// ---------------------------------------------------------------------------
__global__ void k_layer2(const float* __restrict__ b2, float* __restrict__ out) {
    int i = blockIdx.x * blockDim.x + threadIdx.x;
    if (i >= NN) return;

    int start = g_rowstart[i];
    int end   = start + g_deg[i];

    float2 self = *(const float2*)(g_h2 + (size_t)i * DOUT);
    float ax = self.x, ay = self.y;   // self-loop seeds the sum
    float bx = 0.f, by = 0.f, cx = 0.f, cy = 0.f, dx = 0.f, dy = 0.f;

    int j = start;
    for (; j + 3 < end; j += 4) {
        int s0 = __ldg(&g_srcs[j]);
        int s1 = __ldg(&g_srcs[j + 1]);
        int s2 = __ldg(&g_srcs[j + 2]);
        int s3 = __ldg(&g_srcs[j + 3]);
        float2 v0 = __ldg((const float2*)(g_h2 + (size_t)s0 * DOUT));
        float2 v1 = __ldg((const float2*)(g_h2 + (size_t)s1 * DOUT));
        float2 v2 = __ldg((const float2*)(g_h2 + (size_t)s2 * DOUT));
        float2 v3 = __ldg((const float2*)(g_h2 + (size_t)s3 * DOUT));
        ax += v0.x; ay += v0.y;
        bx += v1.x; by += v1.y;
        cx += v2.x; cy += v2.y;
        dx += v3.x; dy += v3.y;
    }
    for (; j < end; j++) {
        int s0 = __ldg(&g_srcs[j]);
        float2 v0 = __ldg((const float2*)(g_h2 + (size_t)s0 * DOUT));
        ax += v0.x; ay += v0.y;
    }
    ax += bx + cx + dx;
    ay += by + cy + dy;

    float di = g_dinv[i];
    float z0 = di * ax + b2[0];
    float z1 = di * ay + b2[1];
    float m   = fmaxf(z0, z1);
    float lse = m + logf(expf(z0 - m) + expf(z1 - m));
    ((float2*)out)[i] = make_float2(z0 - lse, z1 - lse);
}

// ---------------------------------------------------------------------------
extern "C" void kernel_launch(void* const* d_in, const int* in_sizes, int n_in,
                              void* d_out, int out_size) {
    // Identify inputs by element count (order-independent; all counts unique):
    //   x: 12,800,000   edge_index: 6,400,000   W1: 2048   b1: 16   W2: 32   b2: 2
    const float* x  = nullptr;
    const void*  ei = nullptr;
    const float* W1 = nullptr;
    const float* b1 = nullptr;
    const float* W2 = nullptr;
    const float* b2 = nullptr;
    for (int i = 0; i < n_in; i++) {
        switch (in_sizes[i]) {
            case NN * DIN:   x  = (const float*)d_in[i]; break;
            case 2 * NE:     ei = d_in[i];               break;
            case DIN * DH:   W1 = (const float*)d_in[i]; break;
            case DH:         b1 = (const float*)d_in[i]; break;
            case DH * DOUT:  W2 = (const float*)d_in[i]; break;
            case DOUT:       b2 = (const float*)d_in[i]; break;
            default: break;
        }
    }
    float* out = (float*)d_out;  // [N, 2] float32

    const int thr = 256;
    k_detect <<<1, 32>>>((const int*)ei);
    k_zero   <<<(NN + thr - 1) / thr, thr>>>();
    k_prep   <<<(NE + thr - 1) / thr, thr>>>(ei);
    k_scan_a <<<NPART, SCAN_BLK>>>();
    k_scan_b <<<1, 128>>>();
    k_scan_c <<<(NN + thr - 1) / thr, thr>>>();
    k_gemm1  <<<(NN + thr - 1) / thr, thr>>>(x, W1);
    k_reorder<<<(NE + thr - 1) / thr, thr>>>(ei);
    k_layer1 <<<(NN * 4 + thr - 1) / thr, thr>>>(b1, W2);
    k_layer2 <<<(NN + thr - 1) / thr, thr>>>(b2, out);
}

// round 16
// speedup vs baseline: 1.0088x; 1.0088x over previous
#include <cuda_runtime.h>
#include <math.h>

// Problem shape (fixed per reference)
#define NN   100000
#define NE   3200000
#define DIN  128
#define DH   16
#define DOUT 2
#define SCAN_BLK 1024
#define NPART ((NN + SCAN_BLK - 1) / SCAN_BLK)   // 98

// Scratch (static __device__ arrays: allocation-free rule)
static __device__ __align__(16) float g_h1[NN * DH];   // (x@W1)*dinv   6.4 MB
static __device__ __align__(8)  float g_h2[NN * DOUT]; // layer-2 msgs  0.8 MB
static __device__ int   g_srcs[NE];                    // CSR src list 12.8 MB
static __device__ int   g_deg[NN];
static __device__ int   g_incl[NN];                    // block-local inclusive scan
static __device__ int   g_rowstart[NN];
static __device__ int   g_cursor[NN];
static __device__ int   g_part[NPART];
static __device__ float g_dinv[NN];
static __device__ int   g_is64;   // 1 if edge_index is int64, 0 if int32

// ---------------------------------------------------------------------------
// Detect edge_index dtype (int64 vs int32), PARALLEL: 32 lanes each check one
// odd 32-bit word; int64 values < 2^17 have all-zero high words there.
// ---------------------------------------------------------------------------
__global__ void k_detect(const int* __restrict__ ei32) {
    int lane = threadIdx.x;
    int v = ei32[1 + 2 * lane];
    unsigned nz = __ballot_sync(0xFFFFFFFF, v != 0);
    if (lane == 0) g_is64 = (nz == 0) ? 1 : 0;
}

__device__ __forceinline__ void load_edge(const void* ei, int e, int& s, int& d) {
    if (g_is64) {
        s = (int)((const long long*)ei)[e];
        d = (int)((const long long*)ei)[(long long)NE + e];
    } else {
        s = ((const int*)ei)[e];
        d = ((const int*)ei)[NE + e];
    }
}

// ---------------------------------------------------------------------------
__global__ void k_zero() {
    int i = blockIdx.x * blockDim.x + threadIdx.x;
    if (i < NN) g_deg[i] = 0;
}

// Degree count over dst (only edges with both endpoints valid are kept).
__global__ void k_prep(const void* __restrict__ ei) {
    int e = blockIdx.x * blockDim.x + threadIdx.x;
    if (e >= NE) return;
    int s, d;
    load_edge(ei, e, s, d);
    if ((unsigned)s < NN && (unsigned)d < NN) atomicAdd(&g_deg[d], 1);
}

// ---------------------------------------------------------------------------
// Exclusive scan of deg -> rowstart (3 kernels), plus dinv and cursor.
// ---------------------------------------------------------------------------
__global__ void k_scan_a() {
    __shared__ int sh[SCAN_BLK];
    int i = blockIdx.x * SCAN_BLK + threadIdx.x;
    int v = (i < NN) ? g_deg[i] : 0;
    sh[threadIdx.x] = v;
    __syncthreads();
#pragma unroll
    for (int o = 1; o < SCAN_BLK; o <<= 1) {
        int t = (threadIdx.x >= o) ? sh[threadIdx.x - o] : 0;
        __syncthreads();
        sh[threadIdx.x] += t;
        __syncthreads();
    }
    if (i < NN) g_incl[i] = sh[threadIdx.x];
    if (threadIdx.x == SCAN_BLK - 1) g_part[blockIdx.x] = sh[SCAN_BLK - 1];
}

// Parallel exclusive scan of the 98 partials (128-thread Hillis-Steele).
__global__ void k_scan_b() {
    __shared__ int sh[128];
    int t = threadIdx.x;
    int v = (t < NPART) ? g_part[t] : 0;
    sh[t] = v;
    __syncthreads();
#pragma unroll
    for (int o = 1; o < 128; o <<= 1) {
        int u = (t >= o) ? sh[t - o] : 0;
        __syncthreads();
        sh[t] += u;
        __syncthreads();
    }
    if (t < NPART) g_part[t] = sh[t] - v;  // exclusive
}

__global__ void k_scan_c() {
    int i = blockIdx.x * blockDim.x + threadIdx.x;
    if (i >= NN) return;
    int deg = g_deg[i];
    int start = g_incl[i] - deg + g_part[i / SCAN_BLK];
    g_rowstart[i] = start;
    g_cursor[i]   = start;
    g_dinv[i]     = rsqrtf((float)deg + 1.0f);  // +1 = self-loop
}

// ---------------------------------------------------------------------------
// Reorder: group src indices by dst (CSR). Order within a row is arbitrary.
// ---------------------------------------------------------------------------
__global__ void k_reorder(const void* __restrict__ ei) {
    int e = blockIdx.x * blockDim.x + threadIdx.x;
    if (e >= NE) return;
    int s, d;
    load_edge(ei, e, s, d);
    if ((unsigned)s >= NN || (unsigned)d >= NN) return;
    int pos = atomicAdd(&g_cursor[d], 1);
    g_srcs[pos] = s;
}

// ---------------------------------------------------------------------------
// GEMM1: h1' = (x @ W1) * dinv[row]. Separable norm: msg = dinv[d]*h1'[s].
// ---------------------------------------------------------------------------
__global__ void k_gemm1(const float* __restrict__ x, const float* __restrict__ W1) {
    __shared__ float4 Ws[DIN * DH / 4];  // 8 KB, [k][c/4]
    const float4* w4 = (const float4*)W1;
    for (int i = threadIdx.x; i < DIN * DH / 4; i += blockDim.x) Ws[i] = w4[i];
    __syncthreads();

    int row = blockIdx.x * blockDim.x + threadIdx.x;
    if (row >= NN) return;

    const float4* xr = (const float4*)(x + (size_t)row * DIN);
    float4 a0 = make_float4(0.f, 0.f, 0.f, 0.f);
    float4 a1 = a0, a2 = a0, a3 = a0;

#pragma unroll 8
    for (int k4 = 0; k4 < DIN / 4; k4++) {
        float4 xq = __ldg(xr + k4);
        float xv[4] = {xq.x, xq.y, xq.z, xq.w};
#pragma unroll
        for (int kk = 0; kk < 4; kk++) {
            int k = k4 * 4 + kk;
            float v = xv[kk];
            float4 w0 = Ws[k * 4 + 0], w1 = Ws[k * 4 + 1];
            float4 w2 = Ws[k * 4 + 2], w3 = Ws[k * 4 + 3];
            a0.x += v * w0.x; a0.y += v * w0.y; a0.z += v * w0.z; a0.w += v * w0.w;
            a1.x += v * w1.x; a1.y += v * w1.y; a1.z += v * w1.z; a1.w += v * w1.w;
            a2.x += v * w2.x; a2.y += v * w2.y; a2.z += v * w2.z; a2.w += v * w2.w;
            a3.x += v * w3.x; a3.y += v * w3.y; a3.z += v * w3.z; a3.w += v * w3.w;
        }
    }
    float di = g_dinv[row];
    a0.x *= di; a0.y *= di; a0.z *= di; a0.w *= di;
    a1.x *= di; a1.y *= di; a1.z *= di; a1.w *= di;
    a2.x *= di; a2.y *= di; a2.z *= di; a2.w *= di;
    a3.x *= di; a3.y *= di; a3.z *= di; a3.w *= di;
    float4* o = (float4*)(g_h1 + (size_t)row * DH);
    o[0] = a0; o[1] = a1; o[2] = a2; o[3] = a3;
}

// ---------------------------------------------------------------------------
// Layer 1 fused (quad-per-dst): gather-sum h1'[src] in registers (unroll x4
// for MLP), add self, scale by dinv, +b1, relu, @W2, scale by dinv -> h2'.
// ---------------------------------------------------------------------------
__global__ void k_layer1(const float* __restrict__ b1, const float* __restrict__ W2) {
    __shared__ float W2s[DH * DOUT];
    __shared__ float b1s[DH];
    if (threadIdx.x < DH * DOUT) W2s[threadIdx.x] = W2[threadIdx.x];
    if (threadIdx.x < DH)        b1s[threadIdx.x] = b1[threadIdx.x];
    __syncthreads();

    int gid = blockIdx.x * blockDim.x + threadIdx.x;
    int i = gid >> 2;
    int q = gid & 3;
    if (i >= NN) return;

    int start = g_rowstart[i];
    int end   = start + g_deg[i];

    // self-loop contribution (h1'[i]) seeds accumulator 0
    float4 a0 = __ldg((const float4*)(g_h1 + (size_t)i * DH) + q);
    float4 a1 = make_float4(0.f, 0.f, 0.f, 0.f);
    float4 a2 = a1, a3 = a1;

    int j = start;
    for (; j + 3 < end; j += 4) {
        int s0 = __ldg(&g_srcs[j]);
        int s1 = __ldg(&g_srcs[j + 1]);
        int s2 = __ldg(&g_srcs[j + 2]);
        int s3 = __ldg(&g_srcs[j + 3]);
        float4 v0 = __ldg((const float4*)(g_h1 + (size_t)s0 * DH) + q);
        float4 v1 = __ldg((const float4*)(g_h1 + (size_t)s1 * DH) + q);
        float4 v2 = __ldg((const float4*)(g_h1 + (size_t)s2 * DH) + q);
        float4 v3 = __ldg((const float4*)(g_h1 + (size_t)s3 * DH) + q);
        a0.x += v0.x; a0.y += v0.y; a0.z += v0.z; a0.w += v0.w;
        a1.x += v1.x; a1.y += v1.y; a1.z += v1.z; a1.w += v1.w;
        a2.x += v2.x; a2.y += v2.y; a2.z += v2.z; a2.w += v2.w;
        a3.x += v3.x; a3.y += v3.y; a3.z += v3.z; a3.w += v3.w;
    }
    for (; j < end; j++) {
        int s0 = __ldg(&g_srcs[j]);
        float4 v0 = __ldg((const float4*)(g_h1 + (size_t)s0 * DH) + q);
        a0.x += v0.x; a0.y += v0.y; a0.z += v0.z; a0.w += v0.w;
    }
    a0.x += a1.x + a2.x + a3.x;
    a0.y += a1.y + a2.y + a3.y;
    a0.z += a1.z + a2.z + a3.z;
    a0.w += a1.w + a2.w + a3.w;

    float di = g_dinv[i];
    float r0 = fmaxf(di * a0.x + b1s[4 * q + 0], 0.f);
    float r1 = fmaxf(di * a0.y + b1s[4 * q + 1], 0.f);
    float r2 = fmaxf(di * a0.z + b1s[4 * q + 2], 0.f);
    float r3 = fmaxf(di * a0.w + b1s[4 * q + 3], 0.f);

    float h2a = r0 * W2s[(4 * q + 0) * 2 + 0] + r1 * W2s[(4 * q + 1) * 2 + 0]
              + r2 * W2s[(4 * q + 2) * 2 + 0] + r3 * W2s[(4 * q + 3) * 2 + 0];
    float h2b = r0 * W2s[(4 * q + 0) * 2 + 1] + r1 * W2s[(4 * q + 1) * 2 + 1]
              + r2 * W2s[(4 * q + 2) * 2 + 1] + r3 * W2s[(4 * q + 3) * 2 + 1];

    // quad reduction (width-4 shuffles)
    h2a += __shfl_down_sync(0xFFFFFFFF, h2a, 2, 4);
    h2a += __shfl_down_sync(0xFFFFFFFF, h2a, 1, 4);
    h2b += __shfl_down_sync(0xFFFFFFFF, h2b, 2, 4);
    h2b += __shfl_down_sync(0xFFFFFFFF, h2b, 1, 4);

    if (q == 0)
        *(float2*)(g_h2 + (size_t)i * DOUT) = make_float2(h2a * di, h2b * di);
}

// ---------------------------------------------------------------------------
// Layer 2 fused (thread-per-dst): gather-sum h2'[src] (unroll x4), add self,
// scale, +b2, log_softmax, write out.
// ---------------------------------------------------------------------------
__global__ void k_layer2(const float* __restrict__ b2, float* __restrict__ out) {
    int i = blockIdx.x * blockDim.x + threadIdx.x;
    if (i >= NN) return;

    int start = g_rowstart[i];
    int end   = start + g_deg[i];

    float2 self = *(const float2*)(g_h2 + (size_t)i * DOUT);
    float ax = self.x, ay = self.y;   // self-loop seeds the sum
    float bx = 0.f, by = 0.f, cx = 0.f, cy = 0.f, dx = 0.f, dy = 0.f;

    int j = start;
    for (; j + 3 < end; j += 4) {
        int s0 = __ldg(&g_srcs[j]);
        int s1 = __ldg(&g_srcs[j + 1]);
        int s2 = __ldg(&g_srcs[j + 2]);
        int s3 = __ldg(&g_srcs[j + 3]);
        float2 v0 = __ldg((const float2*)(g_h2 + (size_t)s0 * DOUT));
        float2 v1 = __ldg((const float2*)(g_h2 + (size_t)s1 * DOUT));
        float2 v2 = __ldg((const float2*)(g_h2 + (size_t)s2 * DOUT));
        float2 v3 = __ldg((const float2*)(g_h2 + (size_t)s3 * DOUT));
        ax += v0.x; ay += v0.y;
        bx += v1.x; by += v1.y;
        cx += v2.x; cy += v2.y;
        dx += v3.x; dy += v3.y;
    }
    for (; j < end; j++) {
        int s0 = __ldg(&g_srcs[j]);
        float2 v0 = __ldg((const float2*)(g_h2 + (size_t)s0 * DOUT));
        ax += v0.x; ay += v0.y;
    }
    ax += bx + cx + dx;
    ay += by + cy + dy;

    float di = g_dinv[i];
    float z0 = di * ax + b2[0];
    float z1 = di * ay + b2[1];
    float m   = fmaxf(z0, z1);
    float lse = m + logf(expf(z0 - m) + expf(z1 - m));
    ((float2*)out)[i] = make_float2(z0 - lse, z1 - lse);
}

// ---------------------------------------------------------------------------
extern "C" void kernel_launch(void* const* d_in, const int* in_sizes, int n_in,
                              void* d_out, int out_size) {
    // Identify inputs by element count (order-independent; all counts unique):
    //   x: 12,800,000   edge_index: 6,400,000   W1: 2048   b1: 16   W2: 32   b2: 2
    const float* x  = nullptr;
    const void*  ei = nullptr;
    const float* W1 = nullptr;
    const float* b1 = nullptr;
    const float* W2 = nullptr;
    const float* b2 = nullptr;
    for (int i = 0; i < n_in; i++) {
        switch (in_sizes[i]) {
            case NN * DIN:   x  = (const float*)d_in[i]; break;
            case 2 * NE:     ei = d_in[i];               break;
            case DIN * DH:   W1 = (const float*)d_in[i]; break;
            case DH:         b1 = (const float*)d_in[i]; break;
            case DH * DOUT:  W2 = (const float*)d_in[i]; break;
            case DOUT:       b2 = (const float*)d_in[i]; break;
            default: break;
        }
    }
    float* out = (float*)d_out;  // [N, 2] float32

    const int thr = 256;
    k_detect <<<1, 32>>>((const int*)ei);
    k_zero   <<<(NN + thr - 1) / thr, thr>>>();
    k_prep   <<<(NE + thr - 1) / thr, thr>>>(ei);
    k_scan_a <<<NPART, SCAN_BLK>>>();
    k_scan_b <<<1, 128>>>();
    k_scan_c <<<(NN + thr - 1) / thr, thr>>>();
    k_gemm1  <<<(NN + thr - 1) / thr, thr>>>(x, W1);
    k_reorder<<<(NE + thr - 1) / thr, thr>>>(ei);
    k_layer1 <<<(NN * 4 + thr - 1) / thr, thr>>>(b1, W2);
    k_layer2 <<<(NN + thr - 1) / thr, thr>>>(b2, out);
}

// round 17
// speedup vs baseline: 1.1026x; 1.0929x over previous
#include <cuda_runtime.h>
#include <cuda_fp16.h>
#include <math.h>

// Problem shape (fixed per reference)
#define NN   100000
#define NE   3200000
#define DIN  128
#define DH   16
#define DOUT 2
#define SCAN_BLK 1024
#define NPART ((NN + SCAN_BLK - 1) / SCAN_BLK)   // 98

// Scratch (static __device__ arrays: allocation-free rule)
static __device__ __align__(32) __half g_h1h[NN * DH];  // (x@W1)*dinv fp16  3.2 MB
static __device__ __align__(8)  float  g_h2[NN * DOUT]; // layer-2 msgs      0.8 MB
static __device__ int   g_srcs[NE];                     // CSR src list     12.8 MB
static __device__ int   g_deg[NN];
static __device__ int   g_incl[NN];                     // block-local inclusive scan
static __device__ int   g_rowstart[NN];
static __device__ int   g_cursor[NN];
static __device__ int   g_part[NPART];
static __device__ float g_dinv[NN];
static __device__ int   g_is64;   // 1 if edge_index is int64, 0 if int32

// ---------------------------------------------------------------------------
// Detect edge_index dtype (int64 vs int32): 32 lanes each check one odd
// 32-bit word; int64 values < 2^17 have all-zero high words there.
// ---------------------------------------------------------------------------
__global__ void k_detect(const int* __restrict__ ei32) {
    int lane = threadIdx.x;
    int v = ei32[1 + 2 * lane];
    unsigned nz = __ballot_sync(0xFFFFFFFF, v != 0);
    if (lane == 0) g_is64 = (nz == 0) ? 1 : 0;
}

__device__ __forceinline__ void load_edge(const void* ei, int e, int& s, int& d) {
    if (g_is64) {
        s = (int)((const long long*)ei)[e];
        d = (int)((const long long*)ei)[(long long)NE + e];
    } else {
        s = ((const int*)ei)[e];
        d = ((const int*)ei)[NE + e];
    }
}

// ---------------------------------------------------------------------------
__global__ void k_zero() {
    int i = blockIdx.x * blockDim.x + threadIdx.x;
    if (i < NN) g_deg[i] = 0;
}

// Degree count over dst ONLY (reads just the dst half: 25.6 MB not 51.2 MB).
__global__ void k_prep(const void* __restrict__ ei) {
    int e = blockIdx.x * blockDim.x + threadIdx.x;
    if (e >= NE) return;
    int d;
    if (g_is64) d = (int)((const long long*)ei)[(long long)NE + e];
    else        d = ((const int*)ei)[NE + e];
    if ((unsigned)d < NN) atomicAdd(&g_deg[d], 1);
}

// ---------------------------------------------------------------------------
// Exclusive scan of deg -> rowstart (3 kernels), plus dinv and cursor.
// ---------------------------------------------------------------------------
__global__ void k_scan_a() {
    __shared__ int sh[SCAN_BLK];
    int i = blockIdx.x * SCAN_BLK + threadIdx.x;
    int v = (i < NN) ? g_deg[i] : 0;
    sh[threadIdx.x] = v;
    __syncthreads();
#pragma unroll
    for (int o = 1; o < SCAN_BLK; o <<= 1) {
        int t = (threadIdx.x >= o) ? sh[threadIdx.x - o] : 0;
        __syncthreads();
        sh[threadIdx.x] += t;
        __syncthreads();
    }
    if (i < NN) g_incl[i] = sh[threadIdx.x];
    if (threadIdx.x == SCAN_BLK - 1) g_part[blockIdx.x] = sh[SCAN_BLK - 1];
}

__global__ void k_scan_b() {   // parallel exclusive scan of 98 partials
    __shared__ int sh[128];
    int t = threadIdx.x;
    int v = (t < NPART) ? g_part[t] : 0;
    sh[t] = v;
    __syncthreads();
#pragma unroll
    for (int o = 1; o < 128; o <<= 1) {
        int u = (t >= o) ? sh[t - o] : 0;
        __syncthreads();
        sh[t] += u;
        __syncthreads();
    }
    if (t < NPART) g_part[t] = sh[t] - v;  // exclusive
}

__global__ void k_scan_c() {
    int i = blockIdx.x * blockDim.x + threadIdx.x;
    if (i >= NN) return;
    int deg = g_deg[i];
    int start = g_incl[i] - deg + g_part[i / SCAN_BLK];
    g_rowstart[i] = start;
    g_cursor[i]   = start;
    g_dinv[i]     = rsqrtf((float)deg + 1.0f);  // +1 = self-loop
}

// ---------------------------------------------------------------------------
// Reorder: group src indices by dst (CSR). Order within a row is arbitrary.
// ---------------------------------------------------------------------------
__global__ void k_reorder(const void* __restrict__ ei) {
    int e = blockIdx.x * blockDim.x + threadIdx.x;
    if (e >= NE) return;
    int s, d;
    load_edge(ei, e, s, d);
    if ((unsigned)s >= NN || (unsigned)d >= NN) return;
    int pos = atomicAdd(&g_cursor[d], 1);
    g_srcs[pos] = s;
}

// ---------------------------------------------------------------------------
// GEMM1: h1' = (x @ W1) * dinv[row], stored fp16 (32B/row message payload).
// Separable norm: msg = dinv[d] * h1'[s].
// ---------------------------------------------------------------------------
__global__ void k_gemm1(const float* __restrict__ x, const float* __restrict__ W1) {
    __shared__ float4 Ws[DIN * DH / 4];  // 8 KB, [k][c/4]
    const float4* w4 = (const float4*)W1;
    for (int i = threadIdx.x; i < DIN * DH / 4; i += blockDim.x) Ws[i] = w4[i];
    __syncthreads();

    int row = blockIdx.x * blockDim.x + threadIdx.x;
    if (row >= NN) return;

    const float4* xr = (const float4*)(x + (size_t)row * DIN);
    float4 a0 = make_float4(0.f, 0.f, 0.f, 0.f);
    float4 a1 = a0, a2 = a0, a3 = a0;

#pragma unroll 8
    for (int k4 = 0; k4 < DIN / 4; k4++) {
        float4 xq = __ldg(xr + k4);
        float xv[4] = {xq.x, xq.y, xq.z, xq.w};
#pragma unroll
        for (int kk = 0; kk < 4; kk++) {
            int k = k4 * 4 + kk;
            float v = xv[kk];
            float4 w0 = Ws[k * 4 + 0], w1 = Ws[k * 4 + 1];
            float4 w2 = Ws[k * 4 + 2], w3 = Ws[k * 4 + 3];
            a0.x += v * w0.x; a0.y += v * w0.y; a0.z += v * w0.z; a0.w += v * w0.w;
            a1.x += v * w1.x; a1.y += v * w1.y; a1.z += v * w1.z; a1.w += v * w1.w;
            a2.x += v * w2.x; a2.y += v * w2.y; a2.z += v * w2.z; a2.w += v * w2.w;
            a3.x += v * w3.x; a3.y += v * w3.y; a3.z += v * w3.z; a3.w += v * w3.w;
        }
    }
    float di = g_dinv[row];
    __align__(16) __half2 h[8];
    h[0] = __floats2half2_rn(a0.x * di, a0.y * di);
    h[1] = __floats2half2_rn(a0.z * di, a0.w * di);
    h[2] = __floats2half2_rn(a1.x * di, a1.y * di);
    h[3] = __floats2half2_rn(a1.z * di, a1.w * di);
    h[4] = __floats2half2_rn(a2.x * di, a2.y * di);
    h[5] = __floats2half2_rn(a2.z * di, a2.w * di);
    h[6] = __floats2half2_rn(a3.x * di, a3.y * di);
    h[7] = __floats2half2_rn(a3.z * di, a3.w * di);
    uint4* o = (uint4*)(g_h1h + (size_t)row * DH);
    o[0] = *(uint4*)&h[0];
    o[1] = *(uint4*)&h[4];
}

__device__ __forceinline__ void acc_u4(float* acc, uint4 u) {
    __half2* hp = (__half2*)&u;
#pragma unroll
    for (int t = 0; t < 4; t++) {
        float2 f = __half22float2(hp[t]);
        acc[2 * t]     += f.x;
        acc[2 * t + 1] += f.y;
    }
}

// ---------------------------------------------------------------------------
// Layer 1 fused (pair-per-dst): each of 2 lanes owns 8 fp16 columns (16B).
// Gather-sum neighbors in fp32 regs (x4 unroll for MLP), add self, scale by
// dinv, +b1, relu, @W2, pair-reduce, scale by dinv -> h2'.
// ---------------------------------------------------------------------------
__global__ void k_layer1(const float* __restrict__ b1, const float* __restrict__ W2) {
    __shared__ float W2s[DH * DOUT];
    __shared__ float b1s[DH];
    if (threadIdx.x < DH * DOUT) W2s[threadIdx.x] = W2[threadIdx.x];
    if (threadIdx.x < DH)        b1s[threadIdx.x] = b1[threadIdx.x];
    __syncthreads();

    int gid = blockIdx.x * blockDim.x + threadIdx.x;
    int i = gid >> 1;
    int q = gid & 1;
    if (i >= NN) return;

    int start = g_rowstart[i];
    int end   = start + g_deg[i];

    const uint4* base = (const uint4*)g_h1h;  // 2 uint4 per row

    float acc[8] = {0.f, 0.f, 0.f, 0.f, 0.f, 0.f, 0.f, 0.f};
    acc_u4(acc, __ldg(base + (size_t)i * 2 + q));  // self-loop seed

    int j = start;
    for (; j + 3 < end; j += 4) {
        int s0 = __ldg(&g_srcs[j]);
        int s1 = __ldg(&g_srcs[j + 1]);
        int s2 = __ldg(&g_srcs[j + 2]);
        int s3 = __ldg(&g_srcs[j + 3]);
        uint4 u0 = __ldg(base + (size_t)s0 * 2 + q);
        uint4 u1 = __ldg(base + (size_t)s1 * 2 + q);
        uint4 u2 = __ldg(base + (size_t)s2 * 2 + q);
        uint4 u3 = __ldg(base + (size_t)s3 * 2 + q);
        acc_u4(acc, u0);
        acc_u4(acc, u1);
        acc_u4(acc, u2);
        acc_u4(acc, u3);
    }
    for (; j < end; j++) {
        int s0 = __ldg(&g_srcs[j]);
        acc_u4(acc, __ldg(base + (size_t)s0 * 2 + q));
    }

    float di = g_dinv[i];
    float h2a = 0.f, h2b = 0.f;
#pragma unroll
    for (int t = 0; t < 8; t++) {
        int col = q * 8 + t;
        float r = fmaxf(di * acc[t] + b1s[col], 0.f);
        h2a += r * W2s[col * 2 + 0];
        h2b += r * W2s[col * 2 + 1];
    }
    // pair reduction (width-2 shuffle)
    h2a += __shfl_down_sync(0xFFFFFFFF, h2a, 1, 2);
    h2b += __shfl_down_sync(0xFFFFFFFF, h2b, 1, 2);

    if (q == 0)
        *(float2*)(g_h2 + (size_t)i * DOUT) = make_float2(h2a * di, h2b * di);
}

// ---------------------------------------------------------------------------
// Layer 2 fused (thread-per-dst): gather-sum h2'[src] (x4 unroll), add self,
// scale, +b2, log_softmax, write out.
// ---------------------------------------------------------------------------
__global__ void k_layer2(const float* __restrict__ b2, float* __restrict__ out) {
    int i = blockIdx.x * blockDim.x + threadIdx.x;
    if (i >= NN) return;

    int start = g_rowstart[i];
    int end   = start + g_deg[i];

    float2 self = *(const float2*)(g_h2 + (size_t)i * DOUT);
    float ax = self.x, ay = self.y;   // self-loop seeds the sum
    float bx = 0.f, by = 0.f, cx = 0.f, cy = 0.f, dx = 0.f, dy = 0.f;

    int j = start;
    for (; j + 3 < end; j += 4) {
        int s0 = __ldg(&g_srcs[j]);
        int s1 = __ldg(&g_srcs[j + 1]);
        int s2 = __ldg(&g_srcs[j + 2]);
        int s3 = __ldg(&g_srcs[j + 3]);
        float2 v0 = __ldg((const float2*)(g_h2 + (size_t)s0 * DOUT));
        float2 v1 = __ldg((const float2*)(g_h2 + (size_t)s1 * DOUT));
        float2 v2 = __ldg((const float2*)(g_h2 + (size_t)s2 * DOUT));
        float2 v3 = __ldg((const float2*)(g_h2 + (size_t)s3 * DOUT));
        ax += v0.x; ay += v0.y;
        bx += v1.x; by += v1.y;
        cx += v2.x; cy += v2.y;
        dx += v3.x; dy += v3.y;
    }
    for (; j < end; j++) {
        int s0 = __ldg(&g_srcs[j]);
        float2 v0 = __ldg((const float2*)(g_h2 + (size_t)s0 * DOUT));
        ax += v0.x; ay += v0.y;
    }
    ax += bx + cx + dx;
    ay += by + cy + dy;

    float di = g_dinv[i];
    float z0 = di * ax + b2[0];
    float z1 = di * ay + b2[1];
    float m   = fmaxf(z0, z1);
    float lse = m + logf(expf(z0 - m) + expf(z1 - m));
    ((float2*)out)[i] = make_float2(z0 - lse, z1 - lse);
}

// ---------------------------------------------------------------------------
extern "C" void kernel_launch(void* const* d_in, const int* in_sizes, int n_in,
                              void* d_out, int out_size) {
    // Identify inputs by element count (order-independent; all counts unique):
    //   x: 12,800,000   edge_index: 6,400,000   W1: 2048   b1: 16   W2: 32   b2: 2
    const float* x  = nullptr;
    const void*  ei = nullptr;
    const float* W1 = nullptr;
    const float* b1 = nullptr;
    const float* W2 = nullptr;
    const float* b2 = nullptr;
    for (int i = 0; i < n_in; i++) {
        switch (in_sizes[i]) {
            case NN * DIN:   x  = (const float*)d_in[i]; break;
            case 2 * NE:     ei = d_in[i];               break;
            case DIN * DH:   W1 = (const float*)d_in[i]; break;
            case DH:         b1 = (const float*)d_in[i]; break;
            case DH * DOUT:  W2 = (const float*)d_in[i]; break;
            case DOUT:       b2 = (const float*)d_in[i]; break;
            default: break;
        }
    }
    float* out = (float*)d_out;  // [N, 2] float32

    const int thr = 256;
    k_detect <<<1, 32>>>((const int*)ei);
    k_zero   <<<(NN + thr - 1) / thr, thr>>>();
    k_prep   <<<(NE + thr - 1) / thr, thr>>>(ei);
    k_scan_a <<<NPART, SCAN_BLK>>>();
    k_scan_b <<<1, 128>>>();
    k_scan_c <<<(NN + thr - 1) / thr, thr>>>();
    k_gemm1  <<<(NN + thr - 1) / thr, thr>>>(x, W1);
    k_reorder<<<(NE + thr - 1) / thr, thr>>>(ei);
    k_layer1 <<<(NN * 2 + thr - 1) / thr, thr>>>(b1, W2);
    k_layer2 <<<(NN + thr - 1) / thr, thr>>>(b2, out);
}